// round 1
// baseline (speedup 1.0000x reference)
#include <cuda_runtime.h>

// CostVolume correlation:
// out[b,h,j,i] = (1/128) * sum_c L[b,h,j,c] * R[b,h,j-i,c]  for j>=i, else 0
// Shapes: L,R = (8,160,320,128) f32 ; out = (8,160,320,64) f32
//
// Per (b*h, j-tile of 64): dense 64x64 "GEMM" in (j',k') space where
//   i        = (j' - k') & 63
//   k_global = j0 + k'        if k' <= j'   (smem row 64+k')
//   k_global = j0 - 64 + k'   if k' >  j'   (smem row k')
// Rows with k_global < 0 are zero-filled -> outputs for j < i come out 0.

#define WW 320
#define CC 128
#define DD 64
#define TJ 64

__global__ __launch_bounds__(256, 2)
void cost_volume_kernel(const float* __restrict__ L,
                        const float* __restrict__ R,
                        float* __restrict__ out) {
    extern __shared__ float smem[];
    float* Ls = smem;               // [CC][TJ]  : Ls[c*64 + j']
    float* Rs = smem + CC * TJ;     // [CC][128] : Rs[c*128 + s]

    const int jt  = blockIdx.x;     // 0..4
    const int bh  = blockIdx.y;     // 0..1279
    const int j0  = jt * TJ;
    const int tid = threadIdx.x;

    const float* Lg = L + (size_t)bh * WW * CC;
    const float* Rg = R + (size_t)bh * WW * CC;

    // ---- Load L tile (64 rows x 128 c), transposed into Ls[c][j'] ----
    {
        int jp = tid >> 2;   // 0..63
        int cq = tid & 3;    // 0..3
        const float4* src = (const float4*)(Lg + (size_t)(j0 + jp) * CC);
        #pragma unroll
        for (int k = 0; k < 8; k++) {
            int c4 = cq + 4 * k;
            float4 v = src[c4];
            int c = 4 * c4;
            Ls[(c + 0) * TJ + jp] = v.x;
            Ls[(c + 1) * TJ + jp] = v.y;
            Ls[(c + 2) * TJ + jp] = v.z;
            Ls[(c + 3) * TJ + jp] = v.w;
        }
    }
    // ---- Load R tile (rows j0-64 .. j0+63), transposed into Rs[c][s] ----
    {
        int s  = tid >> 1;   // 0..127
        int cp = tid & 1;    // 0..1
        int r  = j0 - 64 + s;
        bool valid = (r >= 0);
        const float4* src = (const float4*)(Rg + (size_t)(valid ? r : 0) * CC);
        #pragma unroll
        for (int k = 0; k < 16; k++) {
            int c4 = cp + 2 * k;
            float4 v = valid ? src[c4] : make_float4(0.f, 0.f, 0.f, 0.f);
            int c = 4 * c4;
            Rs[(c + 0) * 128 + s] = v.x;
            Rs[(c + 1) * 128 + s] = v.y;
            Rs[(c + 2) * 128 + s] = v.z;
            Rs[(c + 3) * 128 + s] = v.w;
        }
    }
    __syncthreads();

    const int tx = tid & 15;    // k' / 4
    const int ty = tid >> 4;    // j' / 4

    float acc[4][4];
    #pragma unroll
    for (int a = 0; a < 4; a++)
        #pragma unroll
        for (int b = 0; b < 4; b++) acc[a][b] = 0.f;

    const float* lsp = Ls + ty * 4;

    if (tx != ty) {
        const int roff = (tx < ty) ? 64 : 0;   // all-lower vs all-upper source
        const float* rsp = Rs + tx * 4 + roff;
        #pragma unroll 8
        for (int c = 0; c < CC; c++) {
            float4 a = *(const float4*)(lsp + c * TJ);
            float4 b = *(const float4*)(rsp + c * 128);
            acc[0][0] += a.x * b.x; acc[0][1] += a.x * b.y; acc[0][2] += a.x * b.z; acc[0][3] += a.x * b.w;
            acc[1][0] += a.y * b.x; acc[1][1] += a.y * b.y; acc[1][2] += a.y * b.z; acc[1][3] += a.y * b.w;
            acc[2][0] += a.z * b.x; acc[2][1] += a.z * b.y; acc[2][2] += a.z * b.z; acc[2][3] += a.z * b.w;
            acc[3][0] += a.w * b.x; acc[3][1] += a.w * b.y; acc[3][2] += a.w * b.z; acc[3][3] += a.w * b.w;
        }
    } else {
        // diagonal thread: micro-tile straddles k'==j'; kk<=jj -> lower source (+64)
        const float* rsp0 = Rs + tx * 4 + 64;  // k' <= j'
        const float* rsp1 = Rs + tx * 4;       // k' >  j'
        #pragma unroll 4
        for (int c = 0; c < CC; c++) {
            float4 a  = *(const float4*)(lsp  + c * TJ);
            float4 b0 = *(const float4*)(rsp0 + c * 128);
            float4 b1 = *(const float4*)(rsp1 + c * 128);
            acc[0][0] += a.x * b0.x; acc[0][1] += a.x * b1.y; acc[0][2] += a.x * b1.z; acc[0][3] += a.x * b1.w;
            acc[1][0] += a.y * b0.x; acc[1][1] += a.y * b0.y; acc[1][2] += a.y * b1.z; acc[1][3] += a.y * b1.w;
            acc[2][0] += a.z * b0.x; acc[2][1] += a.z * b0.y; acc[2][2] += a.z * b0.z; acc[2][3] += a.z * b1.w;
            acc[3][0] += a.w * b0.x; acc[3][1] += a.w * b0.y; acc[3][2] += a.w * b0.z; acc[3][3] += a.w * b0.w;
        }
    }

    // ---- Epilogue: i = (j' - k') & 63, divide by 128 ----
    const float inv = 1.0f / 128.0f;
    float* og = out + ((size_t)bh * WW + j0) * DD;
    #pragma unroll
    for (int jj = 0; jj < 4; jj++) {
        int jp = ty * 4 + jj;
        #pragma unroll
        for (int kk = 0; kk < 4; kk++) {
            int kp = tx * 4 + kk;
            int i = (jp - kp) & 63;
            og[jp * DD + i] = acc[jj][kk] * inv;
        }
    }
}

extern "C" void kernel_launch(void* const* d_in, const int* in_sizes, int n_in,
                              void* d_out, int out_size) {
    const float* left  = (const float*)d_in[0];
    const float* right = (const float*)d_in[1];
    float* out = (float*)d_out;

    const int smem_bytes = (CC * TJ + CC * 128) * sizeof(float);  // 96 KB
    cudaFuncSetAttribute(cost_volume_kernel,
                         cudaFuncAttributeMaxDynamicSharedMemorySize, smem_bytes);

    dim3 grid(WW / TJ, 8 * 160);   // (5, 1280)
    cost_volume_kernel<<<grid, 256, smem_bytes>>>(left, right, out);
}

// round 3
// speedup vs baseline: 1.5227x; 1.5227x over previous
#include <cuda_runtime.h>
#include <cuda_bf16.h>
#include <cstdint>

// CostVolume via mma.sync bf16-split GEMM (legacy HMMA path; tcgen05 is not
// available because the harness compiles through virtual arch compute_103).
//
// out[b,h,j,i] = (1/128) * sum_c L[b,h,j,c]*R[b,h,j-i,c], j>=i else 0.
// L,R: (8,160,320,128) f32 ; out: (8,160,320,64) f32.
//
// Per CTA (bh, kt): D[m=0..127][n=0..63] = sum_c L[kt*64+m][c] * R[kt*64+n][c]
// Output (j = kt*64+m, i = m-n) valid iff 0 <= i <= 63; each out element is
// produced by exactly one (kt, m). fp32 accuracy via split A=Ah+Al, B=Bh+Bl,
// D = Ah*Bh + Al*Bh + Ah*Bl.

#define WW 320
#define CC 128
#define DD 64
#define ROWB 272   // row stride in bytes: 136 bf16 = 128 data + 8 pad (conflict-free ldmatrix)

#define OFF_AH 0
#define OFF_AL (128 * ROWB)            // 34816
#define OFF_BH (OFF_AL + 128 * ROWB)   // 69632
#define OFF_BL (OFF_BH + 64 * ROWB)    // 87040
#define SMEM_TOTAL (OFF_BL + 64 * ROWB) // 104448 (~102 KB)

__device__ __forceinline__ uint32_t smem_u32(const void* p) {
    uint32_t a;
    asm("{ .reg .u64 t; cvta.to.shared.u64 t, %1; cvt.u32.u64 %0, t; }" : "=r"(a) : "l"(p));
    return a;
}

// pack 2 floats -> bf16x2 hi, plus bf16x2 of the residuals (lo)
__device__ __forceinline__ void split2(float x0, float x1, uint32_t& hp, uint32_t& lp) {
    asm("cvt.rn.bf16x2.f32 %0, %1, %2;" : "=r"(hp) : "f"(x1), "f"(x0));
    float h0 = __uint_as_float(hp << 16);
    float h1 = __uint_as_float(hp & 0xFFFF0000u);
    float l0 = x0 - h0;
    float l1 = x1 - h1;
    asm("cvt.rn.bf16x2.f32 %0, %1, %2;" : "=r"(lp) : "f"(l1), "f"(l0));
}

__device__ __forceinline__ void ldsm4(uint32_t& r0, uint32_t& r1, uint32_t& r2,
                                      uint32_t& r3, uint32_t addr) {
    asm volatile("ldmatrix.sync.aligned.m8n8.x4.shared.b16 {%0,%1,%2,%3}, [%4];"
                 : "=r"(r0), "=r"(r1), "=r"(r2), "=r"(r3) : "r"(addr));
}

__device__ __forceinline__ void mma_bf16(float* d, const uint32_t* a,
                                         uint32_t b0, uint32_t b1) {
    asm volatile(
        "mma.sync.aligned.m16n8k16.row.col.f32.bf16.bf16.f32 "
        "{%0,%1,%2,%3}, {%4,%5,%6,%7}, {%8,%9}, {%0,%1,%2,%3};"
        : "+f"(d[0]), "+f"(d[1]), "+f"(d[2]), "+f"(d[3])
        : "r"(a[0]), "r"(a[1]), "r"(a[2]), "r"(a[3]), "r"(b0), "r"(b1));
}

__global__ __launch_bounds__(256, 2)
void cv_mma_kernel(const float* __restrict__ L, const float* __restrict__ R,
                   float* __restrict__ out) {
    extern __shared__ char smem[];
    const uint32_t sb = smem_u32(smem);
    const int tid = threadIdx.x;
    const int wid = tid >> 5;
    const int lid = tid & 31;
    const int kt = blockIdx.x;      // 0..4
    const int bh = blockIdx.y;      // 0..1279

    const float* Lg = L + (size_t)bh * WW * CC;
    const float* Rg = R + (size_t)bh * WW * CC;

    // ---- A: L rows kt*64 .. kt*64+127 (clamped at 319), bf16 hi/lo in smem ----
    #pragma unroll
    for (int it = 0; it < 8; it++) {
        int e = tid + it * 256;
        int m = e >> 4, g = e & 15;      // row m, k-granule g (8 floats)
        int j = kt * 64 + m;
        if (j > WW - 1) j = WW - 1;      // rows j>=320 discarded at store time
        const float4* src = (const float4*)(Lg + (size_t)j * CC + g * 8);
        float4 v0 = __ldg(src), v1 = __ldg(src + 1);
        uint32_t h0, h1, h2, h3, l0, l1, l2, l3;
        split2(v0.x, v0.y, h0, l0);
        split2(v0.z, v0.w, h1, l1);
        split2(v1.x, v1.y, h2, l2);
        split2(v1.z, v1.w, h3, l3);
        int off = m * ROWB + g * 16;
        *(uint4*)(smem + OFF_AH + off) = make_uint4(h0, h1, h2, h3);
        *(uint4*)(smem + OFF_AL + off) = make_uint4(l0, l1, l2, l3);
    }
    // ---- B: R rows kt*64 .. kt*64+63 (always in range) ----
    #pragma unroll
    for (int it = 0; it < 4; it++) {
        int e = tid + it * 256;
        int n = e >> 4, g = e & 15;
        int r = kt * 64 + n;
        const float4* src = (const float4*)(Rg + (size_t)r * CC + g * 8);
        float4 v0 = __ldg(src), v1 = __ldg(src + 1);
        uint32_t h0, h1, h2, h3, l0, l1, l2, l3;
        split2(v0.x, v0.y, h0, l0);
        split2(v0.z, v0.w, h1, l1);
        split2(v1.x, v1.y, h2, l2);
        split2(v1.z, v1.w, h3, l3);
        int off = n * ROWB + g * 16;
        *(uint4*)(smem + OFF_BH + off) = make_uint4(h0, h1, h2, h3);
        *(uint4*)(smem + OFF_BL + off) = make_uint4(l0, l1, l2, l3);
    }
    __syncthreads();

    // ---- Warp tiling: 2 (M) x 4 (N) warps; warp tile 64x16 ----
    const int wm = wid & 1;
    const int wn = wid >> 1;
    const int lrow = lid & 15;              // ldmatrix row within 16-row group
    const int lkb  = (lid >> 4) << 4;       // 0 or 16 bytes (k half)
    const uint32_t aoff = sb + (uint32_t)((wm * 64 + lrow) * ROWB + lkb);
    const uint32_t boff = sb + (uint32_t)((wn * 16 + lrow) * ROWB + lkb);

    float acc[4][2][4];
    #pragma unroll
    for (int mf = 0; mf < 4; mf++)
        #pragma unroll
        for (int nf = 0; nf < 2; nf++)
            #pragma unroll
            for (int c = 0; c < 4; c++) acc[mf][nf][c] = 0.f;

    // terms: Ah*Bh, Al*Bh, Ah*Bl
    const uint32_t abase[3] = {OFF_AH, OFF_AL, OFF_AH};
    const uint32_t bbase[3] = {OFF_BH, OFF_BH, OFF_BL};
    #pragma unroll
    for (int t = 0; t < 3; t++) {
        const uint32_t ab = aoff + abase[t];
        const uint32_t bb = boff + bbase[t];
        #pragma unroll
        for (int ks = 0; ks < 8; ks++) {    // 16 bf16 per k-step
            uint32_t b0, b1, b2, b3;
            ldsm4(b0, b1, b2, b3, bb + ks * 32);
            #pragma unroll
            for (int mf = 0; mf < 4; mf++) {
                uint32_t af[4];
                ldsm4(af[0], af[1], af[2], af[3], ab + mf * 16 * ROWB + ks * 32);
                mma_bf16(acc[mf][0], af, b0, b2);   // n-frag 0: k0/k8 matrices
                mma_bf16(acc[mf][1], af, b1, b3);   // n-frag 1
            }
        }
    }
    __syncthreads();

    // ---- Stage into smem [128][65] f32 (reuses A region), then coalesced store ----
    float* sout = (float*)smem;
    for (int e = tid; e < 128 * 65; e += 256) sout[e] = 0.f;
    __syncthreads();

    const float inv = 1.0f / 128.0f;
    const int mrow = wm * 64 + (lid >> 2);
    const int ncol = wn * 16 + (lid & 3) * 2;
    #pragma unroll
    for (int mf = 0; mf < 4; mf++) {
        #pragma unroll
        for (int nf = 0; nf < 2; nf++) {
            #pragma unroll
            for (int c = 0; c < 4; c++) {
                int m = mrow + mf * 16 + (c >> 1) * 8;
                int n = ncol + nf * 8 + (c & 1);
                int i = m - n;
                if (i >= 0 && i < 64)
                    sout[m * 65 + i] = acc[mf][nf][c] * inv;
            }
        }
    }
    __syncthreads();

    float* og = out + (size_t)bh * WW * DD;
    for (int m2 = wid; m2 < 127; m2 += 8) {
        int j = kt * 64 + m2;
        if (j >= WW) continue;
        int lo2, hi2;
        if (m2 < 64) { lo2 = 0; hi2 = (kt == 0) ? 63 : m2; }  // kt==0: zeros for i>m2
        else         { lo2 = m2 - 63; hi2 = 63; }
        #pragma unroll
        for (int s = 0; s < 2; s++) {
            int i = lid + 32 * s;
            if (i >= lo2 && i <= hi2)
                og[(size_t)j * DD + i] = sout[m2 * 65 + i];
        }
    }
}

extern "C" void kernel_launch(void* const* d_in, const int* in_sizes, int n_in,
                              void* d_out, int out_size) {
    const float* left  = (const float*)d_in[0];
    const float* right = (const float*)d_in[1];
    float* out = (float*)d_out;

    cudaFuncSetAttribute(cv_mma_kernel,
                         cudaFuncAttributeMaxDynamicSharedMemorySize, SMEM_TOTAL);
    dim3 grid(5, 8 * 160);   // (kt, bh)
    cv_mma_kernel<<<grid, 256, SMEM_TOTAL>>>(left, right, out);
}

// round 4
// speedup vs baseline: 2.0360x; 1.3371x over previous
#include <cuda_runtime.h>
#include <cuda_bf16.h>
#include <cstdint>

// CostVolume via mma.sync bf16-split GEMM (HMMA path; tcgen05 unavailable:
// harness compiles through virtual arch compute_103, which rejects sm_103a-only PTX).
//
// out[b,h,j,i] = (1/128) * sum_c L[b,h,j,c]*R[b,h,j-i,c], j>=i else 0.
// Per CTA (bh, kt): D[m<128][n<64] = sum_c L[kt*64+m][c]*R[kt*64+n][c];
// out(j=kt*64+m, i=m-n) valid iff 0<=i<64, each covered exactly once.
// fp32 accuracy: A=Ah+Al, B=Bh+Bl (bf16), D = Ah*Bh + Al*Bh + Ah*Bl.

#define WW 320
#define CC 128
#define DD 64
#define ROWB 272   // 136 bf16: 128 data + 4 pad -> conflict-free ldmatrix phases

#define OFF_AH 0
#define OFF_AL (128 * ROWB)             // 34816
#define OFF_BH (OFF_AL + 128 * ROWB)    // 69632
#define OFF_BL (OFF_BH + 64 * ROWB)     // 87040
#define SMEM_TOTAL (OFF_BL + 64 * ROWB) // 104448

__device__ __forceinline__ uint32_t smem_u32(const void* p) {
    uint32_t a;
    asm("{ .reg .u64 t; cvta.to.shared.u64 t, %1; cvt.u32.u64 %0, t; }" : "=r"(a) : "l"(p));
    return a;
}

__device__ __forceinline__ void split2(float x0, float x1, uint32_t& hp, uint32_t& lp) {
    asm("cvt.rn.bf16x2.f32 %0, %1, %2;" : "=r"(hp) : "f"(x1), "f"(x0));
    float h0 = __uint_as_float(hp << 16);
    float h1 = __uint_as_float(hp & 0xFFFF0000u);
    float l0 = x0 - h0;
    float l1 = x1 - h1;
    asm("cvt.rn.bf16x2.f32 %0, %1, %2;" : "=r"(lp) : "f"(l1), "f"(l0));
}

__device__ __forceinline__ void ldsm4(uint32_t* r, uint32_t addr) {
    asm volatile("ldmatrix.sync.aligned.m8n8.x4.shared.b16 {%0,%1,%2,%3}, [%4];"
                 : "=r"(r[0]), "=r"(r[1]), "=r"(r[2]), "=r"(r[3]) : "r"(addr));
}

__device__ __forceinline__ void mma_bf16(float* d, const uint32_t* a,
                                         uint32_t b0, uint32_t b1) {
    asm volatile(
        "mma.sync.aligned.m16n8k16.row.col.f32.bf16.bf16.f32 "
        "{%0,%1,%2,%3}, {%4,%5,%6,%7}, {%8,%9}, {%0,%1,%2,%3};"
        : "+f"(d[0]), "+f"(d[1]), "+f"(d[2]), "+f"(d[3])
        : "r"(a[0]), "r"(a[1]), "r"(a[2]), "r"(a[3]), "r"(b0), "r"(b1));
}

__global__ __launch_bounds__(256, 2)
void cv_mma_kernel(const float* __restrict__ L, const float* __restrict__ R,
                   float* __restrict__ out) {
    extern __shared__ char smem[];
    const uint32_t sb = smem_u32(smem);
    const int tid = threadIdx.x;
    const int wid = tid >> 5;
    const int lid = tid & 31;
    const int kt = blockIdx.x;      // 0..4
    const int bh = blockIdx.y;      // 0..1279

    const float* Lg = L + (size_t)bh * WW * CC;
    const float* Rg = R + (size_t)bh * WW * CC;

    // ---- Prologue: split fp32 -> bf16 hi/lo tiles in smem ----
    #pragma unroll
    for (int it = 0; it < 8; it++) {
        int e = tid + it * 256;
        int m = e >> 4, g = e & 15;
        int j = kt * 64 + m;
        if (j > WW - 1) j = WW - 1;         // overrun rows discarded at store
        const float4* src = (const float4*)(Lg + (size_t)j * CC + g * 8);
        float4 v0 = __ldg(src), v1 = __ldg(src + 1);
        uint32_t h0, h1, h2, h3, l0, l1, l2, l3;
        split2(v0.x, v0.y, h0, l0);
        split2(v0.z, v0.w, h1, l1);
        split2(v1.x, v1.y, h2, l2);
        split2(v1.z, v1.w, h3, l3);
        int off = m * ROWB + g * 16;
        *(uint4*)(smem + OFF_AH + off) = make_uint4(h0, h1, h2, h3);
        *(uint4*)(smem + OFF_AL + off) = make_uint4(l0, l1, l2, l3);
    }
    #pragma unroll
    for (int it = 0; it < 4; it++) {
        int e = tid + it * 256;
        int n = e >> 4, g = e & 15;
        int r = kt * 64 + n;
        const float4* src = (const float4*)(Rg + (size_t)r * CC + g * 8);
        float4 v0 = __ldg(src), v1 = __ldg(src + 1);
        uint32_t h0, h1, h2, h3, l0, l1, l2, l3;
        split2(v0.x, v0.y, h0, l0);
        split2(v0.z, v0.w, h1, l1);
        split2(v1.x, v1.y, h2, l2);
        split2(v1.z, v1.w, h3, l3);
        int off = n * ROWB + g * 16;
        *(uint4*)(smem + OFF_BH + off) = make_uint4(h0, h1, h2, h3);
        *(uint4*)(smem + OFF_BL + off) = make_uint4(l0, l1, l2, l3);
    }
    __syncthreads();

    // ---- Warp tiling: 4(M) x 2(N) warps, warp tile 32x32 ----
    const int wm = wid & 3;                 // 32-row group
    const int wn = wid >> 2;                // 32-col group
    const int lrow = lid & 15;
    const int lkb  = (lid >> 4) << 4;
    const uint32_t aH = sb + OFF_AH + (uint32_t)((wm * 32 + lrow) * ROWB + lkb);
    const uint32_t aL = sb + OFF_AL + (uint32_t)((wm * 32 + lrow) * ROWB + lkb);
    const uint32_t bH = sb + OFF_BH + (uint32_t)((wn * 32 + lrow) * ROWB + lkb);
    const uint32_t bL = sb + OFF_BL + (uint32_t)((wn * 32 + lrow) * ROWB + lkb);

    float acc[2][4][4];                     // [mf 16-row][nf 8-col][frag]
    #pragma unroll
    for (int mf = 0; mf < 2; mf++)
        #pragma unroll
        for (int nf = 0; nf < 4; nf++)
            #pragma unroll
            for (int c = 0; c < 4; c++) acc[mf][nf][c] = 0.f;

    #pragma unroll
    for (int ks = 0; ks < 8; ks++) {        // 16 bf16 per k-step
        uint32_t bh0[4], bh1[4], bl0[4], bl1[4];
        ldsm4(bh0, bH + ks * 32);
        ldsm4(bh1, bH + 16 * ROWB + ks * 32);
        ldsm4(bl0, bL + ks * 32);
        ldsm4(bl1, bL + 16 * ROWB + ks * 32);
        #pragma unroll
        for (int mf = 0; mf < 2; mf++) {
            uint32_t ah[4], al[4];
            ldsm4(ah, aH + mf * 16 * ROWB + ks * 32);
            ldsm4(al, aL + mf * 16 * ROWB + ks * 32);
            // Ah*Bh
            mma_bf16(acc[mf][0], ah, bh0[0], bh0[2]);
            mma_bf16(acc[mf][1], ah, bh0[1], bh0[3]);
            mma_bf16(acc[mf][2], ah, bh1[0], bh1[2]);
            mma_bf16(acc[mf][3], ah, bh1[1], bh1[3]);
            // Al*Bh
            mma_bf16(acc[mf][0], al, bh0[0], bh0[2]);
            mma_bf16(acc[mf][1], al, bh0[1], bh0[3]);
            mma_bf16(acc[mf][2], al, bh1[0], bh1[2]);
            mma_bf16(acc[mf][3], al, bh1[1], bh1[3]);
            // Ah*Bl
            mma_bf16(acc[mf][0], ah, bl0[0], bl0[2]);
            mma_bf16(acc[mf][1], ah, bl0[1], bl0[3]);
            mma_bf16(acc[mf][2], ah, bl1[0], bl1[2]);
            mma_bf16(acc[mf][3], ah, bl1[1], bl1[3]);
        }
    }
    __syncthreads();

    // ---- Stage into smem [128][65] f32, then coalesced range stores ----
    float* sout = (float*)smem;
    for (int e = tid; e < 128 * 65; e += 256) sout[e] = 0.f;
    __syncthreads();

    const float inv = 1.0f / 128.0f;
    const int mrow = wm * 32 + (lid >> 2);
    const int ncol = wn * 32 + (lid & 3) * 2;
    #pragma unroll
    for (int mf = 0; mf < 2; mf++) {
        #pragma unroll
        for (int nf = 0; nf < 4; nf++) {
            #pragma unroll
            for (int c = 0; c < 4; c++) {
                int m = mrow + mf * 16 + (c >> 1) * 8;
                int n = ncol + nf * 8 + (c & 1);
                int i = m - n;
                if (i >= 0 && i < 64)
                    sout[m * 65 + i] = acc[mf][nf][c] * inv;
            }
        }
    }
    __syncthreads();

    float* og = out + (size_t)bh * WW * DD;
    for (int m2 = wid; m2 < 127; m2 += 8) {
        int j = kt * 64 + m2;
        if (j >= WW) continue;
        int lo2, hi2;
        if (m2 < 64) { lo2 = 0; hi2 = (kt == 0) ? 63 : m2; }  // kt==0: zeros fill i>m2
        else         { lo2 = m2 - 63; hi2 = 63; }
        #pragma unroll
        for (int s = 0; s < 2; s++) {
            int i = lid + 32 * s;
            if (i >= lo2 && i <= hi2)
                og[(size_t)j * DD + i] = sout[m2 * 65 + i];
        }
    }
}

extern "C" void kernel_launch(void* const* d_in, const int* in_sizes, int n_in,
                              void* d_out, int out_size) {
    const float* left  = (const float*)d_in[0];
    const float* right = (const float*)d_in[1];
    float* out = (float*)d_out;

    cudaFuncSetAttribute(cv_mma_kernel,
                         cudaFuncAttributeMaxDynamicSharedMemorySize, SMEM_TOTAL);
    dim3 grid(5, 8 * 160);   // (kt, bh)
    cv_mma_kernel<<<grid, 256, SMEM_TOTAL>>>(left, right, out);
}